// round 3
// baseline (speedup 1.0000x reference)
#include <cuda_runtime.h>
#include <cuda_bf16.h>

using u32 = unsigned int;
using u64 = unsigned long long;

#define BPAIR 4096
#define NROWS 8192
#define DDIM  512
// exp(x/T) = 2^(x * 2*log2(e)),  T = 0.5
#define EXP_SCALE 2.8853900817779268f
#define LN2_F     0.6931471805599453f

// ---------------- device scratch (no allocations allowed) ----------------
__device__ __nv_bfloat16 g_nA[NROWS * DDIM];   // normalized [x1; z2]
__device__ __nv_bfloat16 g_nB[NROWS * DDIM];   // normalized [x2; z1]
__device__ float g_log_partial[128];
__device__ float g_pos_partial[1024];

// ---------------- PTX helpers ----------------
__device__ __forceinline__ u32 smem_u32(const void* p) {
    u32 a;
    asm("{ .reg .u64 t; cvta.to.shared.u64 t, %1; cvt.u32.u64 %0, t; }"
        : "=r"(a) : "l"(p));
    return a;
}
__device__ __forceinline__ float ex2f(float x) {
    float y; asm("ex2.approx.f32 %0, %1;" : "=f"(y) : "f"(x)); return y;
}
__device__ __forceinline__ float lg2f(float x) {
    float y; asm("lg2.approx.f32 %0, %1;" : "=f"(y) : "f"(x)); return y;
}
__device__ __forceinline__ void cp_async16(u32 dst, const void* src) {
    asm volatile("cp.async.cg.shared.global [%0], [%1], 16;"
                 :: "r"(dst), "l"(src) : "memory");
}
#define CP_COMMIT() asm volatile("cp.async.commit_group;" ::: "memory")
#define CP_WAIT0()  asm volatile("cp.async.wait_group 0;" ::: "memory")
#define CP_WAIT1()  asm volatile("cp.async.wait_group 1;" ::: "memory")
#define CP_WAIT2()  asm volatile("cp.async.wait_group 2;" ::: "memory")

__device__ __forceinline__ void ldsm4(u32 (&r)[4], u32 addr) {
    asm volatile("ldmatrix.sync.aligned.m8n8.x4.shared.b16 {%0,%1,%2,%3}, [%4];"
        : "=r"(r[0]), "=r"(r[1]), "=r"(r[2]), "=r"(r[3]) : "r"(addr));
}
__device__ __forceinline__ void mma16816(float (&d)[4], const u32 (&a)[4],
                                         u32 b0, u32 b1) {
    asm volatile(
        "mma.sync.aligned.m16n8k16.row.col.f32.bf16.bf16.f32 "
        "{%0,%1,%2,%3}, {%4,%5,%6,%7}, {%8,%9}, {%0,%1,%2,%3};"
        : "+f"(d[0]), "+f"(d[1]), "+f"(d[2]), "+f"(d[3])
        : "r"(a[0]), "r"(a[1]), "r"(a[2]), "r"(a[3]), "r"(b0), "r"(b1));
}

// ---------------- kernel 1: normalize rows -> bf16 ----------------
__global__ void __launch_bounds__(256) k_normalize(
    const float* __restrict__ x1, const float* __restrict__ x2,
    const float* __restrict__ z1, const float* __restrict__ z2) {
    int wg   = blockIdx.x * 8 + (threadIdx.x >> 5);   // global warp = row id
    int lane = threadIdx.x & 31;
    int m  = wg >> 13;           // 0: matA=[x1;z2], 1: matB=[x2;z1]
    int rr = wg & (NROWS - 1);
    const float* src;
    if (m == 0) src = (rr < BPAIR) ? x1 + (size_t)rr * DDIM : z2 + (size_t)(rr - BPAIR) * DDIM;
    else        src = (rr < BPAIR) ? x2 + (size_t)rr * DDIM : z1 + (size_t)(rr - BPAIR) * DDIM;
    __nv_bfloat16* dst = (m == 0 ? g_nA : g_nB) + (size_t)rr * DDIM;

    float4 v[4];
    float ss = 0.f;
#pragma unroll
    for (int k = 0; k < 4; k++) {
        v[k] = ((const float4*)src)[lane + 32 * k];
        ss += v[k].x * v[k].x + v[k].y * v[k].y + v[k].z * v[k].z + v[k].w * v[k].w;
    }
#pragma unroll
    for (int o = 16; o; o >>= 1) ss += __shfl_xor_sync(0xffffffffu, ss, o);
    float r = rsqrtf(ss);
    __nv_bfloat162* d2 = (__nv_bfloat162*)dst;
#pragma unroll
    for (int k = 0; k < 4; k++) {
        int e = lane + 32 * k;
        d2[2 * e]     = __floats2bfloat162_rn(v[k].x * r, v[k].y * r);
        d2[2 * e + 1] = __floats2bfloat162_rn(v[k].z * r, v[k].w * r);
    }
}

// ---------------- kernel 1b: pair dots (fp32, exact) ----------------
__global__ void __launch_bounds__(256) k_pos(
    const float* __restrict__ x1, const float* __restrict__ x2,
    const float* __restrict__ z1, const float* __restrict__ z2) {
    int wg   = blockIdx.x * 8 + (threadIdx.x >> 5);   // pair id 0..8191
    int lane = threadIdx.x & 31;
    int h = wg >> 12;
    int i = wg & (BPAIR - 1);
    const float* a = (h ? x2 : x1) + (size_t)i * DDIM;
    const float* b = (h ? z1 : z2) + (size_t)i * DDIM;
    float sd = 0.f, sa = 0.f, sb = 0.f;
#pragma unroll
    for (int k = 0; k < 4; k++) {
        float4 va = ((const float4*)a)[lane + 32 * k];
        float4 vb = ((const float4*)b)[lane + 32 * k];
        sd += va.x * vb.x + va.y * vb.y + va.z * vb.z + va.w * vb.w;
        sa += va.x * va.x + va.y * va.y + va.z * va.z + va.w * va.w;
        sb += vb.x * vb.x + vb.y * vb.y + vb.z * vb.z + vb.w * vb.w;
    }
#pragma unroll
    for (int o = 16; o; o >>= 1) {
        sd += __shfl_xor_sync(0xffffffffu, sd, o);
        sa += __shfl_xor_sync(0xffffffffu, sa, o);
        sb += __shfl_xor_sync(0xffffffffu, sb, o);
    }
    __shared__ float sh[8];
    if (lane == 0) sh[threadIdx.x >> 5] = sd * rsqrtf(sa * sb);
    __syncthreads();
    if (threadIdx.x == 0) {
        float s = 0.f;
        for (int j = 0; j < 8; j++) s += sh[j];
        g_pos_partial[blockIdx.x] = s;
    }
}

// ---------------- kernel 2: sim GEMM + streaming exp-rowsum ----------------
// grid = 128 (2 matrices x 64 row-blocks of 128 rows), 256 threads (8 warps).
// Per CTA: C[128 x 8192] = Arow[128 x 512] * M^T, fused exp-rowsum epilogue.
// A row-block resident in smem (8 chunks of 128x64 bf16, XOR-swizzled).
// B streamed in 16KB chunks through a 4-slot cp.async ring (depth-2 prefetch).
// Warp grid 4(M) x 2(N); warp tile 32x64 via m16n8k16 bf16 HMMA.
#define SMEM_BYTES 197632

__global__ void __launch_bounds__(256, 1) k_simsum() {
    extern __shared__ char smem[];
    const int tid  = threadIdx.x;
    const int wid  = tid >> 5;
    const int lane = tid & 31;
    const int bx   = blockIdx.x;
    const int mtx  = bx >> 6;
    const int rb   = bx & 63;
    const __nv_bfloat16* __restrict__ mat = mtx ? g_nB : g_nA;

    const u32 sb     = smem_u32(smem);
    float* red       = (float*)smem;            // [2][128] floats (1024 B)
    const u32 A_base = sb + 1024u;              // 8 chunks x 16KB = 128KB
    const u32 B_base = A_base + 131072u;        // 4 slots  x 16KB = 64KB

    const int warpM = wid >> 1, warpN = wid & 1;
    const int lx7 = lane & 7, l15 = lane & 15;
    const u32 aHi = (u32)(lane >> 4);
    const u32 bSegBit = (u32)((lane >> 3) & 1);

    // ---- prologue: load A row-block [128 x 512] (one cp.async group) ----
    {
        const __nv_bfloat16* abase = mat + (size_t)rb * 128 * DDIM;
#pragma unroll
        for (int t = 0; t < 32; t++) {
            int idx = tid + t * 256;
            int ch = idx >> 10, rem = idx & 1023, r = rem >> 3, sg = rem & 7;
            cp_async16(A_base + (u32)(ch * 16384 + r * 128 + ((sg ^ (r & 7)) << 4)),
                       abase + (size_t)r * DDIM + ch * 64 + sg * 8);
        }
        CP_COMMIT();
    }

    auto issueB = [&](int g) {
        u32 slot = B_base + (u32)(g & 3) * 16384u;
        int jt2 = g >> 3, c2 = g & 7;
        const __nv_bfloat16* src = mat + (size_t)(jt2 * 128) * DDIM + c2 * 64;
#pragma unroll
        for (int t = 0; t < 4; t++) {
            int idx = tid + t * 256;
            int r = idx >> 3, sg = idx & 7;
            cp_async16(slot + (u32)(r * 128 + ((sg ^ (r & 7)) << 4)),
                       src + (size_t)r * DDIM + sg * 8);
        }
        CP_COMMIT();
    };
    issueB(0);
    issueB(1);

    // per-lane invariant smem addressing
    const u32 aRowBase = A_base + (u32)(warpM * 32 + l15) * 128u;
    const u32 bRowOff  = (u32)(warpN * 64 + lx7 + ((lane >> 4) << 3)) * 128u;

    float acc[2][8][4];
#pragma unroll
    for (int mi = 0; mi < 2; mi++)
#pragma unroll
        for (int ni = 0; ni < 8; ni++)
#pragma unroll
            for (int e = 0; e < 4; e++) acc[mi][ni][e] = 0.f;

    float rs[2][2] = {{0.f, 0.f}, {0.f, 0.f}};
    const int qr = lane >> 2, qc = lane & 3;
    const int rowLo0 = warpM * 32 + qr;            // + mi*16 (+8 for hi)
    const int colB0  = warpN * 64 + qc * 2;        // + ni*8 (+1)

#pragma unroll 1
    for (int jt = 0; jt < 64; jt++) {
#pragma unroll 1
        for (int c = 0; c < 8; c++) {
            const int g = jt * 8 + c;
            if (g + 2 < 512) { issueB(g + 2); CP_WAIT2(); }
            else if (g + 1 < 512) { CP_WAIT1(); }
            else { CP_WAIT0(); }
            __syncthreads();

            const u32 aChunk = aRowBase + (u32)c * 16384u;
            const u32 bBase  = B_base + (u32)(g & 3) * 16384u + bRowOff;
#pragma unroll
            for (int ks = 0; ks < 4; ks++) {
                u32 A0[4], A1[4], B0[4], B1[4], B2[4], B3[4];
                const u32 aoff = (((2u * ks + aHi) ^ (u32)lx7) << 4);
                ldsm4(A0, aChunk + aoff);
                ldsm4(A1, aChunk + 2048u + aoff);
                const u32 boff = (((2u * ks + bSegBit) ^ (u32)lx7) << 4);
                ldsm4(B0, bBase + boff);
                ldsm4(B1, bBase + 2048u + boff);
                ldsm4(B2, bBase + 4096u + boff);
                ldsm4(B3, bBase + 6144u + boff);
                mma16816(acc[0][0], A0, B0[0], B0[1]);
                mma16816(acc[0][1], A0, B0[2], B0[3]);
                mma16816(acc[0][2], A0, B1[0], B1[1]);
                mma16816(acc[0][3], A0, B1[2], B1[3]);
                mma16816(acc[0][4], A0, B2[0], B2[1]);
                mma16816(acc[0][5], A0, B2[2], B2[3]);
                mma16816(acc[0][6], A0, B3[0], B3[1]);
                mma16816(acc[0][7], A0, B3[2], B3[3]);
                mma16816(acc[1][0], A1, B0[0], B0[1]);
                mma16816(acc[1][1], A1, B0[2], B0[3]);
                mma16816(acc[1][2], A1, B1[0], B1[1]);
                mma16816(acc[1][3], A1, B1[2], B1[3]);
                mma16816(acc[1][4], A1, B2[0], B2[1]);
                mma16816(acc[1][5], A1, B2[2], B2[3]);
                mma16816(acc[1][6], A1, B3[0], B3[1]);
                mma16816(acc[1][7], A1, B3[2], B3[3]);
            }
        }

        // ---- epilogue for j-tile jt: exp + row-accumulate, reset acc ----
        const bool dg = (jt == rb);
#pragma unroll
        for (int mi = 0; mi < 2; mi++) {
            const int rlo = rowLo0 + mi * 16, rhi = rlo + 8;
#pragma unroll
            for (int ni = 0; ni < 8; ni++) {
                const int colb = colB0 + ni * 8;
                float e0 = ex2f(acc[mi][ni][0] * EXP_SCALE);
                float e1 = ex2f(acc[mi][ni][1] * EXP_SCALE);
                float e2 = ex2f(acc[mi][ni][2] * EXP_SCALE);
                float e3 = ex2f(acc[mi][ni][3] * EXP_SCALE);
                if (dg) {
                    if (colb     == rlo) e0 = 0.f;
                    if (colb + 1 == rlo) e1 = 0.f;
                    if (colb     == rhi) e2 = 0.f;
                    if (colb + 1 == rhi) e3 = 0.f;
                }
                rs[mi][0] += e0 + e1;
                rs[mi][1] += e2 + e3;
                acc[mi][ni][0] = 0.f; acc[mi][ni][1] = 0.f;
                acc[mi][ni][2] = 0.f; acc[mi][ni][3] = 0.f;
            }
        }
    }

    // ---- reduce: quad lanes -> rows, N-warps -> rows, rows -> partial ----
#pragma unroll
    for (int mi = 0; mi < 2; mi++)
#pragma unroll
        for (int h = 0; h < 2; h++) {
            float v = rs[mi][h];
            v += __shfl_xor_sync(0xffffffffu, v, 1);
            v += __shfl_xor_sync(0xffffffffu, v, 2);
            rs[mi][h] = v;
        }
    if (qc == 0) {
#pragma unroll
        for (int mi = 0; mi < 2; mi++)
#pragma unroll
            for (int h = 0; h < 2; h++)
                red[warpN * 128 + rowLo0 + mi * 16 + 8 * h] = rs[mi][h];
    }
    __syncthreads();
    float logv = 0.f;
    if (tid < 128) {
        float S = red[tid] + red[128 + tid];
        logv = lg2f(S) * LN2_F;
    }
    __syncthreads();
    if (tid < 128) red[tid] = logv;
    __syncthreads();
    if (tid < 64) red[tid] += red[tid + 64];
    __syncthreads();
    if (tid < 32) {
        float v = red[tid] + red[tid + 32];
#pragma unroll
        for (int o = 16; o; o >>= 1) v += __shfl_xor_sync(0xffffffffu, v, o);
        if (tid == 0) g_log_partial[bx] = v;
    }
}

// ---------------- kernel 3: final reduction ----------------
__global__ void __launch_bounds__(256) k_final(float* __restrict__ out) {
    __shared__ float rsd[256], rp[256];
    const int t = threadIdx.x;
    float s = 0.f, p = 0.f;
    for (int i = t; i < 128; i += 256) s += g_log_partial[i];
    for (int i = t; i < 1024; i += 256) p += g_pos_partial[i];
    rsd[t] = s; rp[t] = p;
    __syncthreads();
    for (int o = 128; o > 0; o >>= 1) {
        if (t < o) { rsd[t] += rsd[t + o]; rp[t] += rp[t + o]; }
        __syncthreads();
    }
    if (t == 0) {
        // loss = (sum LSE - (2/T)*sum pos) / (2B),  2/T = 4, 2B = 8192
        out[0] = (rsd[0] - 4.0f * rp[0]) / 8192.0f;
    }
}

extern "C" void kernel_launch(void* const* d_in, const int* in_sizes, int n_in,
                              void* d_out, int out_size) {
    const float* x1 = (const float*)d_in[0];
    const float* x2 = (const float*)d_in[1];
    const float* z1 = (const float*)d_in[2];
    const float* z2 = (const float*)d_in[3];
    float* out = (float*)d_out;

    cudaFuncSetAttribute(k_simsum, cudaFuncAttributeMaxDynamicSharedMemorySize,
                         SMEM_BYTES);

    k_normalize<<<2048, 256>>>(x1, x2, z1, z2);
    k_pos<<<1024, 256>>>(x1, x2, z1, z2);
    k_simsum<<<128, 256, SMEM_BYTES>>>();
    k_final<<<1, 256>>>(out);
}